// round 7
// baseline (speedup 1.0000x reference)
#include <cuda_runtime.h>
#include <math.h>

#define BSZ   4
#define NTOK  1024
#define DIN   384
#define SST   16
#define NROWS 4096
#define NCOLS 816
#define COLS_PAD 832

__device__ __align__(16) float g_wpack[DIN * COLS_PAD];
__device__ __align__(16) float g_bias[COLS_PAD];
__device__ __align__(16) float g_xT[DIN * NROWS];
__device__ __align__(16) float g_scratch[COLS_PAD * NROWS];

__device__ __forceinline__ float softplusf(float z) {
    return (z > 20.f) ? z : log1pf(expf(z));
}

// ---------------- packed f32x2 helpers (sm_103a FFMA2 path, PTX-only) ----------------
typedef unsigned long long f2;
__device__ __forceinline__ f2 pk(float lo, float hi) {
    f2 r; asm("mov.b64 %0,{%1,%2};" : "=l"(r) : "f"(lo), "f"(hi)); return r;
}
__device__ __forceinline__ void up2(f2 v, float& lo, float& hi) {
    asm("mov.b64 {%0,%1},%2;" : "=f"(lo), "=f"(hi) : "l"(v));
}
__device__ __forceinline__ f2 fma2(f2 a, f2 b, f2 c) {
    f2 r; asm("fma.rn.f32x2 %0,%1,%2,%3;" : "=l"(r) : "l"(a), "l"(b), "l"(c)); return r;
}
__device__ __forceinline__ f2 mul2(f2 a, f2 b) {
    f2 r; asm("mul.rn.f32x2 %0,%1,%2;" : "=l"(r) : "l"(a), "l"(b)); return r;
}

// ---------------- kernel 0a: pack weights k-major + bias ----------------
__global__ void pack_kernel(const float* __restrict__ dtsW, const float* __restrict__ dtsb,
                            const float* __restrict__ dtdW, const float* __restrict__ dtdb,
                            const float* __restrict__ BW,   const float* __restrict__ CrW,
                            const float* __restrict__ CiW) {
    int i = blockIdx.x * blockDim.x + threadIdx.x;
    if (i >= DIN * COLS_PAD) return;
    int k = i / COLS_PAD;
    int c = i % COLS_PAD;
    float v = 0.f;
    if      (c < 384) v = dtsW[c * DIN + k];
    else if (c < 768) v = dtdW[(c - 384) * DIN + k];
    else if (c < 784) v = BW [k * SST + (c - 768)];
    else if (c < 800) v = CrW[k * SST + (c - 784)];
    else if (c < 816) v = CiW[k * SST + (c - 800)];
    g_wpack[i] = v;
    if (k == 0) {
        float bv = 0.f;
        if (c < 384)      bv = dtsb[c];
        else if (c < 768) bv = dtdb[c - 384];
        g_bias[c] = bv;
    }
}

// ---------------- kernel 0b: transpose x -> xT[d][row] ----------------
__global__ void transpose_x(const float* __restrict__ x) {
    __shared__ float tile[32][33];
    int kb = blockIdx.x * 32;
    int rb = blockIdx.y * 32;
    int tx = threadIdx.x, ty = threadIdx.y;
    #pragma unroll
    for (int i = ty; i < 32; i += 8)
        tile[i][tx] = x[(rb + i) * DIN + kb + tx];
    __syncthreads();
    #pragma unroll
    for (int i = ty; i < 32; i += 8)
        g_xT[(kb + i) * NROWS + rb + tx] = tile[tx][i];
}

// ---------------- kernel 1: fused GEMM, packed accumulators ----------------
#define GBM 64
#define GBN 128
#define GBK 16
__global__ __launch_bounds__(256) void gemm_kernel() {
    __shared__ float Ws[GBK][68];
    __shared__ float Xs[GBK][GBN + 4];
    int tid = threadIdx.x;
    int tx = tid & 15;
    int ty = tid >> 4;
    int cBase = blockIdx.x * GBM;
    int rBase = blockIdx.y * GBN;

    f2 acc2[4][4];
    #pragma unroll
    for (int i = 0; i < 4; i++)
        #pragma unroll
        for (int j = 0; j < 4; j++) acc2[i][j] = pk(0.f, 0.f);

    for (int kB = 0; kB < DIN; kB += GBK) {
        {
            int kk = tid >> 4, cc = (tid & 15) * 4;
            float4 v = *(const float4*)&g_wpack[(kB + kk) * COLS_PAD + cBase + cc];
            *(float4*)&Ws[kk][cc] = v;
        }
        #pragma unroll
        for (int ch = 0; ch < 2; ch++) {
            int idx = tid + ch * 256;
            int kk = idx >> 5, rr = (idx & 31) * 4;
            float4 v = *(const float4*)&g_xT[(kB + kk) * NROWS + rBase + rr];
            *(float4*)&Xs[kk][rr] = v;
        }
        __syncthreads();
        #pragma unroll
        for (int kk = 0; kk < GBK; kk++) {
            float a[4];
            *(float4*)&a[0] = *(const float4*)&Ws[kk][ty * 4];
            float4 x0 = *(const float4*)&Xs[kk][tx * 4];
            float4 x1 = *(const float4*)&Xs[kk][64 + tx * 4];
            f2 b2[4] = { pk(x0.x, x0.y), pk(x0.z, x0.w), pk(x1.x, x1.y), pk(x1.z, x1.w) };
            #pragma unroll
            for (int i = 0; i < 4; i++) {
                f2 a2 = pk(a[i], a[i]);
                #pragma unroll
                for (int j = 0; j < 4; j++)
                    acc2[i][j] = fma2(a2, b2[j], acc2[i][j]);
            }
        }
        __syncthreads();
    }

    #pragma unroll
    for (int i = 0; i < 4; i++) {
        int c = cBase + ty * 4 + i;
        float bv = g_bias[c];
        bool act = (c < 768);
        float o[8];
        #pragma unroll
        for (int j = 0; j < 4; j++) up2(acc2[i][j], o[2 * j], o[2 * j + 1]);
        #pragma unroll
        for (int j = 0; j < 8; j++) {
            float v = o[j];
            if (act) v = fminf(softplusf(v + bv), 0.15f);
            o[j] = v;
        }
        *(float4*)&g_scratch[c * NROWS + rBase + tx * 4]      = *(float4*)&o[0];
        *(float4*)&g_scratch[c * NROWS + rBase + 64 + tx * 4] = *(float4*)&o[4];
    }
}

// ---------------- kernel 2: SSM — packed (re,im) pixels IN SHARED; no shuffles ----------------
// 128 threads per (b,d); thread owns 2 rows x 4 cols. Shared = f2[2][32][34]:
// even row stride keeps 16B alignment for the 2-pixel vector loads.
#define SHS2 34
__global__ __launch_bounds__(128, 4) void ssm_kernel(const float* __restrict__ conv_w,
                                                     const float* __restrict__ ralpha,
                                                     const float* __restrict__ rbeta,
                                                     const float* __restrict__ Dparam,
                                                     const float* __restrict__ A_log,
                                                     float* __restrict__ y) {
    __shared__ f2 sh[2][32][SHS2];

    int d   = blockIdx.x;
    int b   = blockIdx.y;
    int t   = threadIdx.x;          // 0..127
    int R0  = (t >> 3) * 2;
    int lane8 = t & 7;
    int pcb = lane8 * 4;
    int row0 = b * NTOK;
    int n0 = R0 * 32 + pcb;
    int n1 = n0 + 32;

    int rm = (R0 > 0)      ? R0 - 1 : 0;
    int rp = (R0 + 2 < 32) ? R0 + 2 : 31;
    int cl = (pcb > 0)  ? pcb - 1 : 0;
    int cr = (pcb < 28) ? pcb + 4 : 31;

    f2 w2[9];
    #pragma unroll
    for (int i = 0; i < 9; i++) { float wv = conv_w[d * 9 + i]; w2[i] = pk(wv, wv); }
    float alpha = ralpha[d];
    float beta  = rbeta[d];
    float Dp    = Dparam[d];
    const f2 HALF2 = pk(0.5f, 0.5f);

    float xv[8], yacc[8];
    f2 ds2[8], dd2[8];
    {
        float4 a = *(const float4*)&g_xT[d * NROWS + row0 + n0];
        float4 c = *(const float4*)&g_xT[d * NROWS + row0 + n1];
        xv[0]=a.x; xv[1]=a.y; xv[2]=a.z; xv[3]=a.w;
        xv[4]=c.x; xv[5]=c.y; xv[6]=c.z; xv[7]=c.w;
        a = *(const float4*)&g_scratch[d * NROWS + row0 + n0];
        c = *(const float4*)&g_scratch[d * NROWS + row0 + n1];
        ds2[0]=pk(a.x,a.x); ds2[1]=pk(a.y,a.y); ds2[2]=pk(a.z,a.z); ds2[3]=pk(a.w,a.w);
        ds2[4]=pk(c.x,c.x); ds2[5]=pk(c.y,c.y); ds2[6]=pk(c.z,c.z); ds2[7]=pk(c.w,c.w);
        a = *(const float4*)&g_scratch[(384 + d) * NROWS + row0 + n0];
        c = *(const float4*)&g_scratch[(384 + d) * NROWS + row0 + n1];
        dd2[0]=pk(a.x,a.x); dd2[1]=pk(a.y,a.y); dd2[2]=pk(a.z,a.z); dd2[3]=pk(a.w,a.w);
        dd2[4]=pk(c.x,c.x); dd2[5]=pk(c.y,c.y); dd2[6]=pk(c.z,c.z); dd2[7]=pk(c.w,c.w);
    }
    #pragma unroll
    for (int j = 0; j < 8; j++) yacc[j] = xv[j] * Dp;

    int buf = 0;
    for (int s = 0; s < SST; s++) {
        float A = -softplusf(A_log[d * SST + s]);
        f2 A2 = pk(A, A);
        f2 u2[8], hc[8];
        {
            float4 a = *(const float4*)&g_scratch[(768 + s) * NROWS + row0 + n0];
            float4 c = *(const float4*)&g_scratch[(768 + s) * NROWS + row0 + n1];
            u2[0] = pk(xv[0]*a.x, 0.f); u2[1] = pk(xv[1]*a.y, 0.f);
            u2[2] = pk(xv[2]*a.z, 0.f); u2[3] = pk(xv[3]*a.w, 0.f);
            u2[4] = pk(xv[4]*c.x, 0.f); u2[5] = pk(xv[5]*c.y, 0.f);
            u2[6] = pk(xv[6]*c.z, 0.f); u2[7] = pk(xv[7]*c.w, 0.f);
        }
        #pragma unroll
        for (int j = 0; j < 8; j++) hc[j] = u2[j];

        #pragma unroll
        for (int step = 0; step < 2; step++) {
            // publish both owned rows (packed pixels, 16B vector stores)
            *(ulonglong2*)&sh[buf][R0][pcb]       = make_ulonglong2(hc[0], hc[1]);
            *(ulonglong2*)&sh[buf][R0][pcb + 2]   = make_ulonglong2(hc[2], hc[3]);
            *(ulonglong2*)&sh[buf][R0+1][pcb]     = make_ulonglong2(hc[4], hc[5]);
            *(ulonglong2*)&sh[buf][R0+1][pcb + 2] = make_ulonglong2(hc[6], hc[7]);
            __syncthreads();

            // halo rows: packed loads, no pk()
            ulonglong2 Ta = *(const ulonglong2*)&sh[buf][rm][pcb];
            ulonglong2 Tb = *(const ulonglong2*)&sh[buf][rm][pcb + 2];
            f2 Tl = sh[buf][rm][cl];
            f2 Tr = sh[buf][rm][cr];
            ulonglong2 Ba = *(const ulonglong2*)&sh[buf][rp][pcb];
            ulonglong2 Bb = *(const ulonglong2*)&sh[buf][rp][pcb + 2];
            f2 Bl = sh[buf][rp][cl];
            f2 Br = sh[buf][rp][cr];
            // mid-row edge taps straight from shared (replaces 8 SHFL + clamps)
            f2 M0l = sh[buf][R0][cl];
            f2 M0r = sh[buf][R0][cr];
            f2 M1l = sh[buf][R0+1][cl];
            f2 M1r = sh[buf][R0+1][cr];

            f2 T[6]  = { Tl, Ta.x, Ta.y, Tb.x, Tb.y, Tr };
            f2 Bw[6] = { Bl, Ba.x, Ba.y, Bb.x, Bb.y, Br };
            f2 M0[6] = { M0l, hc[0], hc[1], hc[2], hc[3], M0r };
            f2 M1[6] = { M1l, hc[4], hc[5], hc[6], hc[7], M1r };

            f2 hn[8];
            #pragma unroll
            for (int c = 0; c < 4; c++) {
                // row 0 pixel c : T / M0 / M1
                f2 lap = mul2(w2[0], T[c]);
                lap = fma2(w2[1], T[c+1], lap);
                lap = fma2(w2[2], T[c+2], lap);
                lap = fma2(w2[3], M0[c],   lap);
                lap = fma2(w2[4], M0[c+1], lap);
                lap = fma2(w2[5], M0[c+2], lap);
                lap = fma2(w2[6], M1[c],   lap);
                lap = fma2(w2[7], M1[c+1], lap);
                lap = fma2(w2[8], M1[c+2], lap);
                {
                    float hrj, hij; up2(hc[c], hrj, hij);
                    float h2 = fmaf(hrj, hrj, hij * hij);
                    float rs = fmaf(-beta, h2, alpha);
                    f2 f1 = mul2(ds2[c], fma2(A2, hc[c], u2[c]));
                    float lr, li; up2(lap, lr, li);
                    f2 sum = fma2(dd2[c], pk(-li, lr), f1);
                    sum = fma2(hc[c], pk(rs, rs), sum);
                    hn[c] = fma2(HALF2, sum, hc[c]);
                }
                // row 1 pixel c : M0 / M1 / Bw
                f2 lap2 = mul2(w2[0], M0[c]);
                lap2 = fma2(w2[1], M0[c+1], lap2);
                lap2 = fma2(w2[2], M0[c+2], lap2);
                lap2 = fma2(w2[3], M1[c],   lap2);
                lap2 = fma2(w2[4], M1[c+1], lap2);
                lap2 = fma2(w2[5], M1[c+2], lap2);
                lap2 = fma2(w2[6], Bw[c],   lap2);
                lap2 = fma2(w2[7], Bw[c+1], lap2);
                lap2 = fma2(w2[8], Bw[c+2], lap2);
                {
                    int j = 4 + c;
                    float hrj, hij; up2(hc[j], hrj, hij);
                    float h2 = fmaf(hrj, hrj, hij * hij);
                    float rs = fmaf(-beta, h2, alpha);
                    f2 f1 = mul2(ds2[j], fma2(A2, hc[j], u2[j]));
                    float lr, li; up2(lap2, lr, li);
                    f2 sum = fma2(dd2[j], pk(-li, lr), f1);
                    sum = fma2(hc[j], pk(rs, rs), sum);
                    hn[j] = fma2(HALF2, sum, hc[j]);
                }
            }
            #pragma unroll
            for (int j = 0; j < 8; j++) hc[j] = hn[j];
            buf ^= 1;
        }

        // output projection accumulate (scalar, saves registers)
        {
            float4 c0 = *(const float4*)&g_scratch[(784 + s) * NROWS + row0 + n0];
            float4 c1 = *(const float4*)&g_scratch[(784 + s) * NROWS + row0 + n1];
            float4 i0 = *(const float4*)&g_scratch[(800 + s) * NROWS + row0 + n0];
            float4 i1 = *(const float4*)&g_scratch[(800 + s) * NROWS + row0 + n1];
            float hr, hi;
            up2(hc[0], hr, hi); yacc[0] = fmaf(hr, c0.x, fmaf(hi, i0.x, yacc[0]));
            up2(hc[1], hr, hi); yacc[1] = fmaf(hr, c0.y, fmaf(hi, i0.y, yacc[1]));
            up2(hc[2], hr, hi); yacc[2] = fmaf(hr, c0.z, fmaf(hi, i0.z, yacc[2]));
            up2(hc[3], hr, hi); yacc[3] = fmaf(hr, c0.w, fmaf(hi, i0.w, yacc[3]));
            up2(hc[4], hr, hi); yacc[4] = fmaf(hr, c1.x, fmaf(hi, i1.x, yacc[4]));
            up2(hc[5], hr, hi); yacc[5] = fmaf(hr, c1.y, fmaf(hi, i1.y, yacc[5]));
            up2(hc[6], hr, hi); yacc[6] = fmaf(hr, c1.z, fmaf(hi, i1.z, yacc[6]));
            up2(hc[7], hr, hi); yacc[7] = fmaf(hr, c1.w, fmaf(hi, i1.w, yacc[7]));
        }
    }

    #pragma unroll
    for (int j = 0; j < 4; j++) {
        y[(row0 + n0 + j) * DIN + d] = yacc[j];
        y[(row0 + n1 + j) * DIN + d] = yacc[4 + j];
    }
}

// ---------------- launch ----------------
extern "C" void kernel_launch(void* const* d_in, const int* in_sizes, int n_in,
                              void* d_out, int out_size) {
    const float* x      = (const float*)d_in[0];
    const float* dtsW   = (const float*)d_in[1];
    const float* dtsb   = (const float*)d_in[2];
    const float* dtdW   = (const float*)d_in[3];
    const float* dtdb   = (const float*)d_in[4];
    const float* BW     = (const float*)d_in[5];
    const float* CrW    = (const float*)d_in[6];
    const float* CiW    = (const float*)d_in[7];
    const float* Dparam = (const float*)d_in[8];
    const float* A_log  = (const float*)d_in[9];
    const float* conv_w = (const float*)d_in[10];
    const float* ralpha = (const float*)d_in[11];
    const float* rbeta  = (const float*)d_in[12];
    float* y = (float*)d_out;

    pack_kernel<<<(DIN * COLS_PAD + 255) / 256, 256>>>(dtsW, dtsb, dtdW, dtdb, BW, CrW, CiW);
    transpose_x<<<dim3(DIN / 32, NROWS / 32), dim3(32, 8)>>>(x);
    gemm_kernel<<<dim3(COLS_PAD / GBM, NROWS / GBN), 256>>>();
    ssm_kernel<<<dim3(DIN, BSZ), 128>>>(conv_w, ralpha, rbeta, Dparam, A_log, y);
}

// round 8
// speedup vs baseline: 1.1120x; 1.1120x over previous
#include <cuda_runtime.h>
#include <math.h>

#define BSZ   4
#define NTOK  1024
#define DIN   384
#define SST   16
#define NROWS 4096
#define NCOLS 816
#define COLS_PAD 832

__device__ __align__(16) float g_wpack[DIN * COLS_PAD];
__device__ __align__(16) float g_bias[COLS_PAD];
__device__ __align__(16) float g_xT[DIN * NROWS];
__device__ __align__(16) float g_scratch[COLS_PAD * NROWS];

__device__ __forceinline__ float softplusf(float z) {
    return (z > 20.f) ? z : log1pf(expf(z));
}

// ---------------- packed f32x2 helpers ----------------
typedef unsigned long long f2;
__device__ __forceinline__ f2 pk(float lo, float hi) {
    f2 r; asm("mov.b64 %0,{%1,%2};" : "=l"(r) : "f"(lo), "f"(hi)); return r;
}
__device__ __forceinline__ void up2(f2 v, float& lo, float& hi) {
    asm("mov.b64 {%0,%1},%2;" : "=f"(lo), "=f"(hi) : "l"(v));
}
__device__ __forceinline__ f2 fma2(f2 a, f2 b, f2 c) {
    f2 r; asm("fma.rn.f32x2 %0,%1,%2,%3;" : "=l"(r) : "l"(a), "l"(b), "l"(c)); return r;
}
__device__ __forceinline__ f2 mul2(f2 a, f2 b) {
    f2 r; asm("mul.rn.f32x2 %0,%1,%2;" : "=l"(r) : "l"(a), "l"(b)); return r;
}

// ---------------- kernel 0a: pack weights k-major + bias ----------------
__global__ void pack_kernel(const float* __restrict__ dtsW, const float* __restrict__ dtsb,
                            const float* __restrict__ dtdW, const float* __restrict__ dtdb,
                            const float* __restrict__ BW,   const float* __restrict__ CrW,
                            const float* __restrict__ CiW) {
    int i = blockIdx.x * blockDim.x + threadIdx.x;
    if (i >= DIN * COLS_PAD) return;
    int k = i / COLS_PAD;
    int c = i % COLS_PAD;
    float v = 0.f;
    if      (c < 384) v = dtsW[c * DIN + k];
    else if (c < 768) v = dtdW[(c - 384) * DIN + k];
    else if (c < 784) v = BW [k * SST + (c - 768)];
    else if (c < 800) v = CrW[k * SST + (c - 784)];
    else if (c < 816) v = CiW[k * SST + (c - 800)];
    g_wpack[i] = v;
    if (k == 0) {
        float bv = 0.f;
        if (c < 384)      bv = dtsb[c];
        else if (c < 768) bv = dtdb[c - 384];
        g_bias[c] = bv;
    }
}

// ---------------- kernel 0b: transpose x -> xT[d][row] ----------------
__global__ void transpose_x(const float* __restrict__ x) {
    __shared__ float tile[32][33];
    int kb = blockIdx.x * 32;
    int rb = blockIdx.y * 32;
    int tx = threadIdx.x, ty = threadIdx.y;
    #pragma unroll
    for (int i = ty; i < 32; i += 8)
        tile[i][tx] = x[(rb + i) * DIN + kb + tx];
    __syncthreads();
    #pragma unroll
    for (int i = ty; i < 32; i += 8)
        g_xT[(kb + i) * NROWS + rb + tx] = tile[tx][i];
}

// ---------------- kernel 1: fused GEMM, packed accumulators ----------------
#define GBM 64
#define GBN 128
#define GBK 16
__global__ __launch_bounds__(256) void gemm_kernel() {
    __shared__ float Ws[GBK][68];
    __shared__ float Xs[GBK][GBN + 4];
    int tid = threadIdx.x;
    int tx = tid & 15;
    int ty = tid >> 4;
    int cBase = blockIdx.x * GBM;
    int rBase = blockIdx.y * GBN;

    f2 acc2[4][4];
    #pragma unroll
    for (int i = 0; i < 4; i++)
        #pragma unroll
        for (int j = 0; j < 4; j++) acc2[i][j] = pk(0.f, 0.f);

    for (int kB = 0; kB < DIN; kB += GBK) {
        {
            int kk = tid >> 4, cc = (tid & 15) * 4;
            float4 v = *(const float4*)&g_wpack[(kB + kk) * COLS_PAD + cBase + cc];
            *(float4*)&Ws[kk][cc] = v;
        }
        #pragma unroll
        for (int ch = 0; ch < 2; ch++) {
            int idx = tid + ch * 256;
            int kk = idx >> 5, rr = (idx & 31) * 4;
            float4 v = *(const float4*)&g_xT[(kB + kk) * NROWS + rBase + rr];
            *(float4*)&Xs[kk][rr] = v;
        }
        __syncthreads();
        #pragma unroll
        for (int kk = 0; kk < GBK; kk++) {
            float a[4];
            *(float4*)&a[0] = *(const float4*)&Ws[kk][ty * 4];
            float4 x0 = *(const float4*)&Xs[kk][tx * 4];
            float4 x1 = *(const float4*)&Xs[kk][64 + tx * 4];
            f2 b2[4] = { pk(x0.x, x0.y), pk(x0.z, x0.w), pk(x1.x, x1.y), pk(x1.z, x1.w) };
            #pragma unroll
            for (int i = 0; i < 4; i++) {
                f2 a2 = pk(a[i], a[i]);
                #pragma unroll
                for (int j = 0; j < 4; j++)
                    acc2[i][j] = fma2(a2, b2[j], acc2[i][j]);
            }
        }
        __syncthreads();
    }

    #pragma unroll
    for (int i = 0; i < 4; i++) {
        int c = cBase + ty * 4 + i;
        float bv = g_bias[c];
        bool act = (c < 768);
        float o[8];
        #pragma unroll
        for (int j = 0; j < 4; j++) up2(acc2[i][j], o[2 * j], o[2 * j + 1]);
        #pragma unroll
        for (int j = 0; j < 8; j++) {
            float v = o[j];
            if (act) v = fminf(softplusf(v + bv), 0.15f);
            o[j] = v;
        }
        *(float4*)&g_scratch[c * NROWS + rBase + tx * 4]      = *(float4*)&o[0];
        *(float4*)&g_scratch[c * NROWS + rBase + 64 + tx * 4] = *(float4*)&o[4];
    }
}

// ---------------- kernel 2: SSM — scalar shared planes (conflict-free) + packed registers ----------------
// 128 threads per (b,d); thread owns 2 rows x 4 cols. One barrier/step.
// Shared: scalar planes stride 36 (float banks distinct for all access patterns).
// Registers: h packed (re,im); all broadcast constants pre-packed outside the step loop.
#define SHS 36
__global__ __launch_bounds__(128, 4) void ssm_kernel(const float* __restrict__ conv_w,
                                                     const float* __restrict__ ralpha,
                                                     const float* __restrict__ rbeta,
                                                     const float* __restrict__ Dparam,
                                                     const float* __restrict__ A_log,
                                                     float* __restrict__ y) {
    __shared__ float shR[2][32][SHS];
    __shared__ float shI[2][32][SHS];

    int d   = blockIdx.x;
    int b   = blockIdx.y;
    int t   = threadIdx.x;
    int R0  = (t >> 3) * 2;
    int lane8 = t & 7;
    int pcb = lane8 * 4;
    int row0 = b * NTOK;
    int n0 = R0 * 32 + pcb;
    int n1 = n0 + 32;

    int rm = (R0 > 0)      ? R0 - 1 : 0;
    int rp = (R0 + 2 < 32) ? R0 + 2 : 31;
    int cl = (pcb > 0)  ? pcb - 1 : 0;
    int cr = (pcb < 28) ? pcb + 4 : 31;

    f2 w2[9];
    #pragma unroll
    for (int i = 0; i < 9; i++) { float wv = conv_w[d * 9 + i]; w2[i] = pk(wv, wv); }
    float alpha = ralpha[d];
    float beta  = rbeta[d];
    float Dp    = Dparam[d];
    const f2 HALF2 = pk(0.5f, 0.5f);

    float xv[8], yacc[8];
    f2 ds2[8], dd2[8];
    {
        float4 a = *(const float4*)&g_xT[d * NROWS + row0 + n0];
        float4 c = *(const float4*)&g_xT[d * NROWS + row0 + n1];
        xv[0]=a.x; xv[1]=a.y; xv[2]=a.z; xv[3]=a.w;
        xv[4]=c.x; xv[5]=c.y; xv[6]=c.z; xv[7]=c.w;
        a = *(const float4*)&g_scratch[d * NROWS + row0 + n0];
        c = *(const float4*)&g_scratch[d * NROWS + row0 + n1];
        ds2[0]=pk(a.x,a.x); ds2[1]=pk(a.y,a.y); ds2[2]=pk(a.z,a.z); ds2[3]=pk(a.w,a.w);
        ds2[4]=pk(c.x,c.x); ds2[5]=pk(c.y,c.y); ds2[6]=pk(c.z,c.z); ds2[7]=pk(c.w,c.w);
        a = *(const float4*)&g_scratch[(384 + d) * NROWS + row0 + n0];
        c = *(const float4*)&g_scratch[(384 + d) * NROWS + row0 + n1];
        dd2[0]=pk(a.x,a.x); dd2[1]=pk(a.y,a.y); dd2[2]=pk(a.z,a.z); dd2[3]=pk(a.w,a.w);
        dd2[4]=pk(c.x,c.x); dd2[5]=pk(c.y,c.y); dd2[6]=pk(c.z,c.z); dd2[7]=pk(c.w,c.w);
    }
    #pragma unroll
    for (int j = 0; j < 8; j++) yacc[j] = xv[j] * Dp;

    int buf = 0;
    for (int s = 0; s < SST; s++) {
        float A = -softplusf(A_log[d * SST + s]);
        f2 A2 = pk(A, A);
        f2 u2[8], hc[8];
        {
            float4 a = *(const float4*)&g_scratch[(768 + s) * NROWS + row0 + n0];
            float4 c = *(const float4*)&g_scratch[(768 + s) * NROWS + row0 + n1];
            u2[0] = pk(xv[0]*a.x, 0.f); u2[1] = pk(xv[1]*a.y, 0.f);
            u2[2] = pk(xv[2]*a.z, 0.f); u2[3] = pk(xv[3]*a.w, 0.f);
            u2[4] = pk(xv[4]*c.x, 0.f); u2[5] = pk(xv[5]*c.y, 0.f);
            u2[6] = pk(xv[6]*c.z, 0.f); u2[7] = pk(xv[7]*c.w, 0.f);
        }
        #pragma unroll
        for (int j = 0; j < 8; j++) hc[j] = u2[j];

        #pragma unroll
        for (int step = 0; step < 2; step++) {
            // publish owned rows to scalar planes (8 up2, 4 STS.128)
            {
                float a0,b0,a1,b1,a2,b2,a3,b3;
                up2(hc[0],a0,b0); up2(hc[1],a1,b1); up2(hc[2],a2,b2); up2(hc[3],a3,b3);
                *(float4*)&shR[buf][R0][pcb] = make_float4(a0,a1,a2,a3);
                *(float4*)&shI[buf][R0][pcb] = make_float4(b0,b1,b2,b3);
                up2(hc[4],a0,b0); up2(hc[5],a1,b1); up2(hc[6],a2,b2); up2(hc[7],a3,b3);
                *(float4*)&shR[buf][R0+1][pcb] = make_float4(a0,a1,a2,a3);
                *(float4*)&shI[buf][R0+1][pcb] = make_float4(b0,b1,b2,b3);
            }
            __syncthreads();

            // halo rows (conflict-free scalar loads), pack into pairs
            float4 tR4 = *(const float4*)&shR[buf][rm][pcb];
            float4 tI4 = *(const float4*)&shI[buf][rm][pcb];
            float  tRl = shR[buf][rm][cl], tIl = shI[buf][rm][cl];
            float  tRr = shR[buf][rm][cr], tIr = shI[buf][rm][cr];
            float4 bR4 = *(const float4*)&shR[buf][rp][pcb];
            float4 bI4 = *(const float4*)&shI[buf][rp][pcb];
            float  bRl = shR[buf][rp][cl], bIl = shI[buf][rp][cl];
            float  bRr = shR[buf][rp][cr], bIr = shI[buf][rp][cr];
            // mid-row edge taps from shared (replaces SHFL+SEL path)
            float  m0Rl = shR[buf][R0][cl],   m0Il = shI[buf][R0][cl];
            float  m0Rr = shR[buf][R0][cr],   m0Ir = shI[buf][R0][cr];
            float  m1Rl = shR[buf][R0+1][cl], m1Il = shI[buf][R0+1][cl];
            float  m1Rr = shR[buf][R0+1][cr], m1Ir = shI[buf][R0+1][cr];

            f2 T[6]  = { pk(tRl,tIl), pk(tR4.x,tI4.x), pk(tR4.y,tI4.y),
                         pk(tR4.z,tI4.z), pk(tR4.w,tI4.w), pk(tRr,tIr) };
            f2 Bw[6] = { pk(bRl,bIl), pk(bR4.x,bI4.x), pk(bR4.y,bI4.y),
                         pk(bR4.z,bI4.z), pk(bR4.w,bI4.w), pk(bRr,bIr) };
            f2 M0[6] = { pk(m0Rl,m0Il), hc[0], hc[1], hc[2], hc[3], pk(m0Rr,m0Ir) };
            f2 M1[6] = { pk(m1Rl,m1Il), hc[4], hc[5], hc[6], hc[7], pk(m1Rr,m1Ir) };

            f2 hn[8];
            #pragma unroll
            for (int c = 0; c < 4; c++) {
                // row 0 pixel c : T / M0 / M1
                f2 lap = mul2(w2[0], T[c]);
                lap = fma2(w2[1], T[c+1], lap);
                lap = fma2(w2[2], T[c+2], lap);
                lap = fma2(w2[3], M0[c],   lap);
                lap = fma2(w2[4], M0[c+1], lap);
                lap = fma2(w2[5], M0[c+2], lap);
                lap = fma2(w2[6], M1[c],   lap);
                lap = fma2(w2[7], M1[c+1], lap);
                lap = fma2(w2[8], M1[c+2], lap);
                {
                    float hrj, hij; up2(hc[c], hrj, hij);
                    float h2 = fmaf(hrj, hrj, hij * hij);
                    float rs = fmaf(-beta, h2, alpha);
                    f2 f1 = mul2(ds2[c], fma2(A2, hc[c], u2[c]));
                    float lr, li; up2(lap, lr, li);
                    f2 sum = fma2(dd2[c], pk(-li, lr), f1);
                    sum = fma2(hc[c], pk(rs, rs), sum);
                    hn[c] = fma2(HALF2, sum, hc[c]);
                }
                // row 1 pixel c : M0 / M1 / Bw
                f2 lap2 = mul2(w2[0], M0[c]);
                lap2 = fma2(w2[1], M0[c+1], lap2);
                lap2 = fma2(w2[2], M0[c+2], lap2);
                lap2 = fma2(w2[3], M1[c],   lap2);
                lap2 = fma2(w2[4], M1[c+1], lap2);
                lap2 = fma2(w2[5], M1[c+2], lap2);
                lap2 = fma2(w2[6], Bw[c],   lap2);
                lap2 = fma2(w2[7], Bw[c+1], lap2);
                lap2 = fma2(w2[8], Bw[c+2], lap2);
                {
                    int j = 4 + c;
                    float hrj, hij; up2(hc[j], hrj, hij);
                    float h2 = fmaf(hrj, hrj, hij * hij);
                    float rs = fmaf(-beta, h2, alpha);
                    f2 f1 = mul2(ds2[j], fma2(A2, hc[j], u2[j]));
                    float lr, li; up2(lap2, lr, li);
                    f2 sum = fma2(dd2[j], pk(-li, lr), f1);
                    sum = fma2(hc[j], pk(rs, rs), sum);
                    hn[j] = fma2(HALF2, sum, hc[j]);
                }
            }
            #pragma unroll
            for (int j = 0; j < 8; j++) hc[j] = hn[j];
            buf ^= 1;
        }

        // output projection accumulate (scalar)
        {
            float4 c0 = *(const float4*)&g_scratch[(784 + s) * NROWS + row0 + n0];
            float4 c1 = *(const float4*)&g_scratch[(784 + s) * NROWS + row0 + n1];
            float4 i0 = *(const float4*)&g_scratch[(800 + s) * NROWS + row0 + n0];
            float4 i1 = *(const float4*)&g_scratch[(800 + s) * NROWS + row0 + n1];
            float hr, hi;
            up2(hc[0], hr, hi); yacc[0] = fmaf(hr, c0.x, fmaf(hi, i0.x, yacc[0]));
            up2(hc[1], hr, hi); yacc[1] = fmaf(hr, c0.y, fmaf(hi, i0.y, yacc[1]));
            up2(hc[2], hr, hi); yacc[2] = fmaf(hr, c0.z, fmaf(hi, i0.z, yacc[2]));
            up2(hc[3], hr, hi); yacc[3] = fmaf(hr, c0.w, fmaf(hi, i0.w, yacc[3]));
            up2(hc[4], hr, hi); yacc[4] = fmaf(hr, c1.x, fmaf(hi, i1.x, yacc[4]));
            up2(hc[5], hr, hi); yacc[5] = fmaf(hr, c1.y, fmaf(hi, i1.y, yacc[5]));
            up2(hc[6], hr, hi); yacc[6] = fmaf(hr, c1.z, fmaf(hi, i1.z, yacc[6]));
            up2(hc[7], hr, hi); yacc[7] = fmaf(hr, c1.w, fmaf(hi, i1.w, yacc[7]));
        }
    }

    #pragma unroll
    for (int j = 0; j < 4; j++) {
        y[(row0 + n0 + j) * DIN + d] = yacc[j];
        y[(row0 + n1 + j) * DIN + d] = yacc[4 + j];
    }
}

// ---------------- launch ----------------
extern "C" void kernel_launch(void* const* d_in, const int* in_sizes, int n_in,
                              void* d_out, int out_size) {
    const float* x      = (const float*)d_in[0];
    const float* dtsW   = (const float*)d_in[1];
    const float* dtsb   = (const float*)d_in[2];
    const float* dtdW   = (const float*)d_in[3];
    const float* dtdb   = (const float*)d_in[4];
    const float* BW     = (const float*)d_in[5];
    const float* CrW    = (const float*)d_in[6];
    const float* CiW    = (const float*)d_in[7];
    const float* Dparam = (const float*)d_in[8];
    const float* A_log  = (const float*)d_in[9];
    const float* conv_w = (const float*)d_in[10];
    const float* ralpha = (const float*)d_in[11];
    const float* rbeta  = (const float*)d_in[12];
    float* y = (float*)d_out;

    pack_kernel<<<(DIN * COLS_PAD + 255) / 256, 256>>>(dtsW, dtsb, dtdW, dtdb, BW, CrW, CiW);
    transpose_x<<<dim3(DIN / 32, NROWS / 32), dim3(32, 8)>>>(x);
    gemm_kernel<<<dim3(COLS_PAD / GBM, NROWS / GBN), 256>>>();
    ssm_kernel<<<dim3(DIN, BSZ), 128>>>(conv_w, ralpha, rbeta, Dparam, A_log, y);
}

// round 9
// speedup vs baseline: 1.1535x; 1.0374x over previous
#include <cuda_runtime.h>
#include <math.h>

#define BSZ   4
#define NTOK  1024
#define DIN   384
#define SST   16
#define NROWS 4096
#define NCOLS 816
#define COLS_PAD 832

__device__ __align__(16) float g_wpack[DIN * COLS_PAD];
__device__ __align__(16) float g_bias[COLS_PAD];
__device__ __align__(16) float g_xT[DIN * NROWS];
__device__ __align__(16) float g_scratch[COLS_PAD * NROWS];

__device__ __forceinline__ float softplusf(float z) {
    return (z > 20.f) ? z : log1pf(expf(z));
}

// ---------------- packed f32x2 helpers ----------------
typedef unsigned long long f2;
__device__ __forceinline__ f2 pk(float lo, float hi) {
    f2 r; asm("mov.b64 %0,{%1,%2};" : "=l"(r) : "f"(lo), "f"(hi)); return r;
}
__device__ __forceinline__ void up2(f2 v, float& lo, float& hi) {
    asm("mov.b64 {%0,%1},%2;" : "=f"(lo), "=f"(hi) : "l"(v));
}
__device__ __forceinline__ f2 fma2(f2 a, f2 b, f2 c) {
    f2 r; asm("fma.rn.f32x2 %0,%1,%2,%3;" : "=l"(r) : "l"(a), "l"(b), "l"(c)); return r;
}
__device__ __forceinline__ f2 mul2(f2 a, f2 b) {
    f2 r; asm("mul.rn.f32x2 %0,%1,%2;" : "=l"(r) : "l"(a), "l"(b)); return r;
}

// ---------------- kernel 0a: pack weights k-major + bias ----------------
__global__ void pack_kernel(const float* __restrict__ dtsW, const float* __restrict__ dtsb,
                            const float* __restrict__ dtdW, const float* __restrict__ dtdb,
                            const float* __restrict__ BW,   const float* __restrict__ CrW,
                            const float* __restrict__ CiW) {
    int i = blockIdx.x * blockDim.x + threadIdx.x;
    if (i >= DIN * COLS_PAD) return;
    int k = i / COLS_PAD;
    int c = i % COLS_PAD;
    float v = 0.f;
    if      (c < 384) v = dtsW[c * DIN + k];
    else if (c < 768) v = dtdW[(c - 384) * DIN + k];
    else if (c < 784) v = BW [k * SST + (c - 768)];
    else if (c < 800) v = CrW[k * SST + (c - 784)];
    else if (c < 816) v = CiW[k * SST + (c - 800)];
    g_wpack[i] = v;
    if (k == 0) {
        float bv = 0.f;
        if (c < 384)      bv = dtsb[c];
        else if (c < 768) bv = dtdb[c - 384];
        g_bias[c] = bv;
    }
}

// ---------------- kernel 0b: transpose x -> xT[d][row] ----------------
__global__ void transpose_x(const float* __restrict__ x) {
    __shared__ float tile[32][33];
    int kb = blockIdx.x * 32;
    int rb = blockIdx.y * 32;
    int tx = threadIdx.x, ty = threadIdx.y;
    #pragma unroll
    for (int i = ty; i < 32; i += 8)
        tile[i][tx] = x[(rb + i) * DIN + kb + tx];
    __syncthreads();
    #pragma unroll
    for (int i = ty; i < 32; i += 8)
        g_xT[(kb + i) * NROWS + rb + tx] = tile[tx][i];
}

// ---------------- kernel 1: GEMM, 8x8 per thread (LDS/fma balanced) ----------------
// Tile 64 cols x 128 rows x 16 k, 128 threads. Thread: cols ty*8..+7,
// rows tx*4..+3 and 64+tx*4..+3 (dense LDS.128 patterns).
#define GBM 64
#define GBN 128
#define GBK 16
__global__ __launch_bounds__(128) void gemm_kernel() {
    __shared__ float Ws[GBK][68];
    __shared__ float Xs[GBK][GBN + 4];
    int tid = threadIdx.x;
    int tx = tid & 15;
    int ty = tid >> 4;
    int cBase = blockIdx.x * GBM;
    int rBase = blockIdx.y * GBN;

    f2 acc2[8][4];   // [col i][rowpair j]: j=0..1 -> rows tx*4+2j.., j=2..3 -> 64+tx*4+..
    #pragma unroll
    for (int i = 0; i < 8; i++)
        #pragma unroll
        for (int j = 0; j < 4; j++) acc2[i][j] = pk(0.f, 0.f);

    for (int kB = 0; kB < DIN; kB += GBK) {
        #pragma unroll
        for (int ch = 0; ch < 2; ch++) {     // Ws: 256 float4, 2 per thread
            int idx = tid + ch * 128;
            int kk = idx >> 4, cc = (idx & 15) * 4;
            *(float4*)&Ws[kk][cc] = *(const float4*)&g_wpack[(kB + kk) * COLS_PAD + cBase + cc];
        }
        #pragma unroll
        for (int ch = 0; ch < 4; ch++) {     // Xs: 512 float4, 4 per thread
            int idx = tid + ch * 128;
            int kk = idx >> 5, rr = (idx & 31) * 4;
            *(float4*)&Xs[kk][rr] = *(const float4*)&g_xT[(kB + kk) * NROWS + rBase + rr];
        }
        __syncthreads();
        #pragma unroll
        for (int kk = 0; kk < GBK; kk++) {
            float a[8];
            *(float4*)&a[0] = *(const float4*)&Ws[kk][ty * 8];
            *(float4*)&a[4] = *(const float4*)&Ws[kk][ty * 8 + 4];
            float4 x0 = *(const float4*)&Xs[kk][tx * 4];
            float4 x1 = *(const float4*)&Xs[kk][64 + tx * 4];
            f2 b2[4] = { pk(x0.x, x0.y), pk(x0.z, x0.w), pk(x1.x, x1.y), pk(x1.z, x1.w) };
            #pragma unroll
            for (int i = 0; i < 8; i++) {
                f2 a2 = pk(a[i], a[i]);
                #pragma unroll
                for (int j = 0; j < 4; j++)
                    acc2[i][j] = fma2(a2, b2[j], acc2[i][j]);
            }
        }
        __syncthreads();
    }

    #pragma unroll
    for (int i = 0; i < 8; i++) {
        int c = cBase + ty * 8 + i;
        float bv = g_bias[c];
        bool act = (c < 768);
        float o[8];
        #pragma unroll
        for (int j = 0; j < 4; j++) up2(acc2[i][j], o[2 * j], o[2 * j + 1]);
        #pragma unroll
        for (int j = 0; j < 8; j++) {
            float v = o[j];
            if (act) v = fminf(softplusf(v + bv), 0.15f);
            o[j] = v;
        }
        *(float4*)&g_scratch[c * NROWS + rBase + tx * 4]      = *(float4*)&o[0];
        *(float4*)&g_scratch[c * NROWS + rBase + 64 + tx * 4] = *(float4*)&o[4];
    }
}

// ---------------- kernel 2: SSM — R5 layout (SHFL edges) + hoisted packed constants ----------------
#define SHS 36
__global__ __launch_bounds__(128, 4) void ssm_kernel(const float* __restrict__ conv_w,
                                                     const float* __restrict__ ralpha,
                                                     const float* __restrict__ rbeta,
                                                     const float* __restrict__ Dparam,
                                                     const float* __restrict__ A_log,
                                                     float* __restrict__ y) {
    __shared__ float shR[2][32][SHS];
    __shared__ float shI[2][32][SHS];

    int d   = blockIdx.x;
    int b   = blockIdx.y;
    int t   = threadIdx.x;
    int R0  = (t >> 3) * 2;
    int lane8 = t & 7;
    int pcb = lane8 * 4;
    int row0 = b * NTOK;
    int n0 = R0 * 32 + pcb;
    int n1 = n0 + 32;

    int rm = (R0 > 0)      ? R0 - 1 : 0;
    int rp = (R0 + 2 < 32) ? R0 + 2 : 31;

    f2 w2[9];
    #pragma unroll
    for (int i = 0; i < 9; i++) { float wv = conv_w[d * 9 + i]; w2[i] = pk(wv, wv); }
    float alpha = ralpha[d];
    float beta  = rbeta[d];
    float Dp    = Dparam[d];
    const f2 HALF2 = pk(0.5f, 0.5f);

    float xv[8], yacc[8];
    f2 ds2[8], dd2[8];
    {
        float4 a = *(const float4*)&g_xT[d * NROWS + row0 + n0];
        float4 c = *(const float4*)&g_xT[d * NROWS + row0 + n1];
        xv[0]=a.x; xv[1]=a.y; xv[2]=a.z; xv[3]=a.w;
        xv[4]=c.x; xv[5]=c.y; xv[6]=c.z; xv[7]=c.w;
        a = *(const float4*)&g_scratch[d * NROWS + row0 + n0];
        c = *(const float4*)&g_scratch[d * NROWS + row0 + n1];
        ds2[0]=pk(a.x,a.x); ds2[1]=pk(a.y,a.y); ds2[2]=pk(a.z,a.z); ds2[3]=pk(a.w,a.w);
        ds2[4]=pk(c.x,c.x); ds2[5]=pk(c.y,c.y); ds2[6]=pk(c.z,c.z); ds2[7]=pk(c.w,c.w);
        a = *(const float4*)&g_scratch[(384 + d) * NROWS + row0 + n0];
        c = *(const float4*)&g_scratch[(384 + d) * NROWS + row0 + n1];
        dd2[0]=pk(a.x,a.x); dd2[1]=pk(a.y,a.y); dd2[2]=pk(a.z,a.z); dd2[3]=pk(a.w,a.w);
        dd2[4]=pk(c.x,c.x); dd2[5]=pk(c.y,c.y); dd2[6]=pk(c.z,c.z); dd2[7]=pk(c.w,c.w);
    }
    #pragma unroll
    for (int j = 0; j < 8; j++) yacc[j] = xv[j] * Dp;

    int buf = 0;
    for (int s = 0; s < SST; s++) {
        float A = -softplusf(A_log[d * SST + s]);
        f2 A2 = pk(A, A);
        f2 u2[8], hc[8];
        {
            float4 a = *(const float4*)&g_scratch[(768 + s) * NROWS + row0 + n0];
            float4 c = *(const float4*)&g_scratch[(768 + s) * NROWS + row0 + n1];
            u2[0] = pk(xv[0]*a.x, 0.f); u2[1] = pk(xv[1]*a.y, 0.f);
            u2[2] = pk(xv[2]*a.z, 0.f); u2[3] = pk(xv[3]*a.w, 0.f);
            u2[4] = pk(xv[4]*c.x, 0.f); u2[5] = pk(xv[5]*c.y, 0.f);
            u2[6] = pk(xv[6]*c.z, 0.f); u2[7] = pk(xv[7]*c.w, 0.f);
        }
        #pragma unroll
        for (int j = 0; j < 8; j++) hc[j] = u2[j];

        #pragma unroll
        for (int step = 0; step < 2; step++) {
            // publish owned rows to scalar planes
            {
                float a0,b0,a1,b1,a2,b2,a3,b3;
                up2(hc[0],a0,b0); up2(hc[1],a1,b1); up2(hc[2],a2,b2); up2(hc[3],a3,b3);
                *(float4*)&shR[buf][R0][pcb] = make_float4(a0,a1,a2,a3);
                *(float4*)&shI[buf][R0][pcb] = make_float4(b0,b1,b2,b3);
                up2(hc[4],a0,b0); up2(hc[5],a1,b1); up2(hc[6],a2,b2); up2(hc[7],a3,b3);
                *(float4*)&shR[buf][R0+1][pcb] = make_float4(a0,a1,a2,a3);
                *(float4*)&shI[buf][R0+1][pcb] = make_float4(b0,b1,b2,b3);
            }
            __syncthreads();

            // halo rows (conflict-free scalar loads; cl/cr clamped)
            int cl = (pcb > 0)  ? pcb - 1 : 0;
            int cr = (pcb < 28) ? pcb + 4 : 31;
            float4 tR4 = *(const float4*)&shR[buf][rm][pcb];
            float4 tI4 = *(const float4*)&shI[buf][rm][pcb];
            float  tRl = shR[buf][rm][cl], tIl = shI[buf][rm][cl];
            float  tRr = shR[buf][rm][cr], tIr = shI[buf][rm][cr];
            float4 bR4 = *(const float4*)&shR[buf][rp][pcb];
            float4 bI4 = *(const float4*)&shI[buf][rp][pcb];
            float  bRl = shR[buf][rp][cl], bIl = shI[buf][rp][cl];
            float  bRr = shR[buf][rp][cr], bIr = shI[buf][rp][cr];

            // mid-row edge taps via SHFL (R5 winner path)
            float h0r,h0i,h3r,h3i,h4r,h4i,h7r,h7i;
            up2(hc[0],h0r,h0i); up2(hc[3],h3r,h3i);
            up2(hc[4],h4r,h4i); up2(hc[7],h7r,h7i);
            float e0lr = __shfl_up_sync(0xffffffffu,   h3r, 1);
            float e0li = __shfl_up_sync(0xffffffffu,   h3i, 1);
            float e0rr = __shfl_down_sync(0xffffffffu, h0r, 1);
            float e0ri = __shfl_down_sync(0xffffffffu, h0i, 1);
            float e1lr = __shfl_up_sync(0xffffffffu,   h7r, 1);
            float e1li = __shfl_up_sync(0xffffffffu,   h7i, 1);
            float e1rr = __shfl_down_sync(0xffffffffu, h4r, 1);
            float e1ri = __shfl_down_sync(0xffffffffu, h4i, 1);
            if (lane8 == 0) { e0lr=h0r; e0li=h0i; e1lr=h4r; e1li=h4i; }
            if (lane8 == 7) { e0rr=h3r; e0ri=h3i; e1rr=h7r; e1ri=h7i; }

            f2 T[6]  = { pk(tRl,tIl), pk(tR4.x,tI4.x), pk(tR4.y,tI4.y),
                         pk(tR4.z,tI4.z), pk(tR4.w,tI4.w), pk(tRr,tIr) };
            f2 Bw[6] = { pk(bRl,bIl), pk(bR4.x,bI4.x), pk(bR4.y,bI4.y),
                         pk(bR4.z,bI4.z), pk(bR4.w,bI4.w), pk(bRr,bIr) };
            f2 M0[6] = { pk(e0lr,e0li), hc[0], hc[1], hc[2], hc[3], pk(e0rr,e0ri) };
            f2 M1[6] = { pk(e1lr,e1li), hc[4], hc[5], hc[6], hc[7], pk(e1rr,e1ri) };

            f2 hn[8];
            #pragma unroll
            for (int c = 0; c < 4; c++) {
                f2 lap = mul2(w2[0], T[c]);
                lap = fma2(w2[1], T[c+1], lap);
                lap = fma2(w2[2], T[c+2], lap);
                lap = fma2(w2[3], M0[c],   lap);
                lap = fma2(w2[4], M0[c+1], lap);
                lap = fma2(w2[5], M0[c+2], lap);
                lap = fma2(w2[6], M1[c],   lap);
                lap = fma2(w2[7], M1[c+1], lap);
                lap = fma2(w2[8], M1[c+2], lap);
                {
                    float hrj, hij; up2(hc[c], hrj, hij);
                    float h2 = fmaf(hrj, hrj, hij * hij);
                    float rs = fmaf(-beta, h2, alpha);
                    f2 f1 = mul2(ds2[c], fma2(A2, hc[c], u2[c]));
                    float lr, li; up2(lap, lr, li);
                    f2 sum = fma2(dd2[c], pk(-li, lr), f1);
                    sum = fma2(hc[c], pk(rs, rs), sum);
                    hn[c] = fma2(HALF2, sum, hc[c]);
                }
                f2 lap2 = mul2(w2[0], M0[c]);
                lap2 = fma2(w2[1], M0[c+1], lap2);
                lap2 = fma2(w2[2], M0[c+2], lap2);
                lap2 = fma2(w2[3], M1[c],   lap2);
                lap2 = fma2(w2[4], M1[c+1], lap2);
                lap2 = fma2(w2[5], M1[c+2], lap2);
                lap2 = fma2(w2[6], Bw[c],   lap2);
                lap2 = fma2(w2[7], Bw[c+1], lap2);
                lap2 = fma2(w2[8], Bw[c+2], lap2);
                {
                    int j = 4 + c;
                    float hrj, hij; up2(hc[j], hrj, hij);
                    float h2 = fmaf(hrj, hrj, hij * hij);
                    float rs = fmaf(-beta, h2, alpha);
                    f2 f1 = mul2(ds2[j], fma2(A2, hc[j], u2[j]));
                    float lr, li; up2(lap2, lr, li);
                    f2 sum = fma2(dd2[j], pk(-li, lr), f1);
                    sum = fma2(hc[j], pk(rs, rs), sum);
                    hn[j] = fma2(HALF2, sum, hc[j]);
                }
            }
            #pragma unroll
            for (int j = 0; j < 8; j++) hc[j] = hn[j];
            buf ^= 1;
        }

        // output projection accumulate
        {
            float4 c0 = *(const float4*)&g_scratch[(784 + s) * NROWS + row0 + n0];
            float4 c1 = *(const float4*)&g_scratch[(784 + s) * NROWS + row0 + n1];
            float4 i0 = *(const float4*)&g_scratch[(800 + s) * NROWS + row0 + n0];
            float4 i1 = *(const float4*)&g_scratch[(800 + s) * NROWS + row0 + n1];
            float hr, hi;
            up2(hc[0], hr, hi); yacc[0] = fmaf(hr, c0.x, fmaf(hi, i0.x, yacc[0]));
            up2(hc[1], hr, hi); yacc[1] = fmaf(hr, c0.y, fmaf(hi, i0.y, yacc[1]));
            up2(hc[2], hr, hi); yacc[2] = fmaf(hr, c0.z, fmaf(hi, i0.z, yacc[2]));
            up2(hc[3], hr, hi); yacc[3] = fmaf(hr, c0.w, fmaf(hi, i0.w, yacc[3]));
            up2(hc[4], hr, hi); yacc[4] = fmaf(hr, c1.x, fmaf(hi, i1.x, yacc[4]));
            up2(hc[5], hr, hi); yacc[5] = fmaf(hr, c1.y, fmaf(hi, i1.y, yacc[5]));
            up2(hc[6], hr, hi); yacc[6] = fmaf(hr, c1.z, fmaf(hi, i1.z, yacc[6]));
            up2(hc[7], hr, hi); yacc[7] = fmaf(hr, c1.w, fmaf(hi, i1.w, yacc[7]));
        }
    }

    #pragma unroll
    for (int j = 0; j < 4; j++) {
        y[(row0 + n0 + j) * DIN + d] = yacc[j];
        y[(row0 + n1 + j) * DIN + d] = yacc[4 + j];
    }
}

// ---------------- launch ----------------
extern "C" void kernel_launch(void* const* d_in, const int* in_sizes, int n_in,
                              void* d_out, int out_size) {
    const float* x      = (const float*)d_in[0];
    const float* dtsW   = (const float*)d_in[1];
    const float* dtsb   = (const float*)d_in[2];
    const float* dtdW   = (const float*)d_in[3];
    const float* dtdb   = (const float*)d_in[4];
    const float* BW     = (const float*)d_in[5];
    const float* CrW    = (const float*)d_in[6];
    const float* CiW    = (const float*)d_in[7];
    const float* Dparam = (const float*)d_in[8];
    const float* A_log  = (const float*)d_in[9];
    const float* conv_w = (const float*)d_in[10];
    const float* ralpha = (const float*)d_in[11];
    const float* rbeta  = (const float*)d_in[12];
    float* y = (float*)d_out;

    pack_kernel<<<(DIN * COLS_PAD + 255) / 256, 256>>>(dtsW, dtsb, dtdW, dtdb, BW, CrW, CiW);
    transpose_x<<<dim3(DIN / 32, NROWS / 32), dim3(32, 8)>>>(x);
    gemm_kernel<<<dim3(COLS_PAD / GBM, NROWS / GBN), 128>>>();
    ssm_kernel<<<dim3(DIN, BSZ), 128>>>(conv_w, ralpha, rbeta, Dparam, A_log, y);
}